// round 2
// baseline (speedup 1.0000x reference)
#include <cuda_runtime.h>
#include <cstdint>

#define N_PTS 262144
#define P_PL  128
#define D_F   64
#define EPSV  1e-5f

#define PN ((size_t)P_PL * (size_t)N_PTS)   // 33,554,432

// Scratch (sanctioned: __device__ globals, no runtime allocation)
__device__ float g_h2[N_PTS * D_F];      // 67 MB
__device__ float g_scores[N_PTS];        // 1 MB

// ---------------------------------------------------------------------------
// packed f32x2 helpers (sm_100+ PTX; ptxas never emits FFMA2 from plain C++)
// ---------------------------------------------------------------------------
__device__ __forceinline__ void ffma2(unsigned long long& d,
                                      unsigned long long a,
                                      unsigned long long b) {
    asm("fma.rn.f32x2 %0, %1, %2, %0;" : "+l"(d) : "l"(a), "l"(b));
}
// d = d * s + t   (packed BN)
__device__ __forceinline__ void ffma2_bn(unsigned long long& d,
                                         unsigned long long s,
                                         unsigned long long t) {
    asm("fma.rn.f32x2 %0, %0, %1, %2;" : "+l"(d) : "l"(s), "l"(t));
}
__device__ __forceinline__ unsigned long long pk2(float lo, float hi) {
    unsigned long long r;
    asm("mov.b64 %0, {%1, %2};" : "=l"(r) : "f"(lo), "f"(hi));
    return r;
}
__device__ __forceinline__ void upk2(unsigned long long v, float& lo, float& hi) {
    asm("mov.b64 {%0, %1}, %2;" : "=f"(lo), "=f"(hi) : "l"(v));
}

// ---------------------------------------------------------------------------
// Kernel 0: zero the on_feat/off_feat output region (d_out is poisoned)
// ---------------------------------------------------------------------------
__global__ void k_init(float* __restrict__ feat_out) {
    int i = blockIdx.x * blockDim.x + threadIdx.x;
    if (i < 2 * P_PL * D_F) feat_out[i] = 0.0f;
}

// ---------------------------------------------------------------------------
// Kernel 1: per-point MLP with packed f32x2 FMAs (channel-pair packing).
// One thread per point, 128 threads/block.
// ---------------------------------------------------------------------------
#define MLP_T 128

__global__ __launch_bounds__(MLP_T)
void k_mlp(const float* __restrict__ feature,
           const float* __restrict__ feature_geo,
           const float* __restrict__ w1, const float* __restrict__ b1,
           const float* __restrict__ g1, const float* __restrict__ be1,
           const float* __restrict__ m1, const float* __restrict__ v1,
           const float* __restrict__ w2, const float* __restrict__ b2,
           const float* __restrict__ g2, const float* __restrict__ be2,
           const float* __restrict__ m2, const float* __restrict__ v2,
           const float* __restrict__ w3, const float* __restrict__ b3)
{
    __shared__ __align__(16) float w1s[128 * 64];   // [k][d]
    __shared__ __align__(16) float w2s[64 * 64];    // [k][d]
    __shared__ __align__(16) float s1s[64], t1s[64], s2s[64], t2s[64], w3s[64];
    __shared__ float b3s;

    const int tid = threadIdx.x;
    for (int j = tid; j < 2048; j += MLP_T) ((float4*)w1s)[j] = ((const float4*)w1)[j];
    for (int j = tid; j < 1024; j += MLP_T) ((float4*)w2s)[j] = ((const float4*)w2)[j];
    if (tid < 64) {
        float s = g1[tid] * rsqrtf(v1[tid] + EPSV);
        s1s[tid] = s;
        t1s[tid] = (b1[tid] - m1[tid]) * s + be1[tid];
        s = g2[tid] * rsqrtf(v2[tid] + EPSV);
        s2s[tid] = s;
        t2s[tid] = (b2[tid] - m2[tid]) * s + be2[tid];
        w3s[tid] = w3[tid];
    }
    if (tid == 0) b3s = b3[0];
    __syncthreads();

    const int i = blockIdx.x * MLP_T + tid;

    // ---- layer 1: acc[dv] packs outputs (2dv, 2dv+1) ----
    unsigned long long acc[32];
#pragma unroll
    for (int d = 0; d < 32; d++) acc[d] = 0ull;

    const float4* fv = (const float4*)feature + (size_t)i * 16;
    const float4* gv = (const float4*)feature_geo + (size_t)i * 16;

#pragma unroll 1
    for (int q = 0; q < 16; q++) {
        float4 f = fv[q];
#pragma unroll
        for (int kk = 0; kk < 4; kk++) {
            float fk = (kk == 0) ? f.x : (kk == 1) ? f.y : (kk == 2) ? f.z : f.w;
            unsigned long long fp = pk2(fk, fk);
            const ulonglong2* wr = (const ulonglong2*)&w1s[(q * 4 + kk) * 64];
#pragma unroll
            for (int dv = 0; dv < 16; dv++) {
                ulonglong2 w = wr[dv];
                ffma2(acc[2 * dv + 0], fp, w.x);
                ffma2(acc[2 * dv + 1], fp, w.y);
            }
        }
    }
#pragma unroll 1
    for (int q = 0; q < 16; q++) {
        float4 f = gv[q];
#pragma unroll
        for (int kk = 0; kk < 4; kk++) {
            float fk = (kk == 0) ? f.x : (kk == 1) ? f.y : (kk == 2) ? f.z : f.w;
            unsigned long long fp = pk2(fk, fk);
            const ulonglong2* wr = (const ulonglong2*)&w1s[(64 + q * 4 + kk) * 64];
#pragma unroll
            for (int dv = 0; dv < 16; dv++) {
                ulonglong2 w = wr[dv];
                ffma2(acc[2 * dv + 0], fp, w.x);
                ffma2(acc[2 * dv + 1], fp, w.y);
            }
        }
    }

    // ---- BN + ReLU -> h1 scalars ----
    float h1[64];
#pragma unroll
    for (int dv = 0; dv < 32; dv++) {
        unsigned long long sp = *(const unsigned long long*)&s1s[2 * dv];
        unsigned long long tp = *(const unsigned long long*)&t1s[2 * dv];
        ffma2_bn(acc[dv], sp, tp);
        float x, y;
        upk2(acc[dv], x, y);
        h1[2 * dv + 0] = fmaxf(x, 0.0f);
        h1[2 * dv + 1] = fmaxf(y, 0.0f);
    }

    // ---- layer 2 in two halves of 32 outputs ----
    unsigned long long score2 = 0ull;
#pragma unroll 1
    for (int half = 0; half < 2; half++) {
        unsigned long long a2[16];
#pragma unroll
        for (int d = 0; d < 16; d++) a2[d] = 0ull;
#pragma unroll
        for (int k = 0; k < 64; k++) {
            unsigned long long hp = pk2(h1[k], h1[k]);
            const ulonglong2* wr = (const ulonglong2*)&w2s[k * 64 + half * 32];
#pragma unroll
            for (int dv = 0; dv < 8; dv++) {
                ulonglong2 w = wr[dv];
                ffma2(a2[2 * dv + 0], hp, w.x);
                ffma2(a2[2 * dv + 1], hp, w.y);
            }
        }
        // BN + ReLU + score accumulation + packed store
        ulonglong2* o2 = (ulonglong2*)&g_h2[(size_t)i * 64 + half * 32];
#pragma unroll
        for (int dv = 0; dv < 16; dv++) {
            const int d0 = half * 32 + dv * 2;
            unsigned long long sp = *(const unsigned long long*)&s2s[d0];
            unsigned long long tp = *(const unsigned long long*)&t2s[d0];
            ffma2_bn(a2[dv], sp, tp);
            float x, y;
            upk2(a2[dv], x, y);
            x = fmaxf(x, 0.0f);
            y = fmaxf(y, 0.0f);
            a2[dv] = pk2(x, y);
            unsigned long long wp = *(const unsigned long long*)&w3s[d0];
            ffma2(score2, a2[dv], wp);
        }
#pragma unroll
        for (int j = 0; j < 8; j++)
            o2[j] = make_ulonglong2(a2[2 * j], a2[2 * j + 1]);
    }
    float slo, shi;
    upk2(score2, slo, shi);
    g_scores[i] = fmaxf(slo + shi + b3s, 0.0f);
}

// ---------------------------------------------------------------------------
// Kernel 2: masks + 4 big outputs + masked max-pool via ballots
// Grid-stride over 512-point chunks; 512 threads/block; 1 block/SM (smem).
// ---------------------------------------------------------------------------
#define K2_THREADS 512
#define CHUNK 512
#define NCHUNK (N_PTS / CHUNK)   // 512

#define SM_HS      0
#define SM_ACCON   (SM_HS + CHUNK * 64)
#define SM_ACCOFF  (SM_ACCON + 8192)
#define SM_SBON    (SM_ACCOFF + 8192)           // as u32
#define SM_SBOFF   (SM_SBON + 2048)
#define SM_PN      (SM_SBOFF + 2048)
#define SM_PMIN    (SM_PN + 384)
#define SM_PMAX    (SM_PMIN + 384)
#define SM_OFF     (SM_PMAX + 384)
#define SM_CENT    (SM_OFF + 128)
#define SM_TOTALF  (SM_CENT + 4)
#define K2_SMEM_BYTES (SM_TOTALF * 4)

__global__ __launch_bounds__(K2_THREADS)
void k_mask(const float* __restrict__ xyz,
            const float* __restrict__ centers,
            const float* __restrict__ plane_center,
            const float* __restrict__ plane_normal,
            const float* __restrict__ plane_min,
            const float* __restrict__ plane_max,
            float* __restrict__ out)
{
    extern __shared__ float sm[];
    float*    hs     = sm + SM_HS;
    float*    accOn  = sm + SM_ACCON;
    float*    accOff = sm + SM_ACCOFF;
    unsigned* sbOn   = (unsigned*)(sm + SM_SBON);
    unsigned* sbOff  = (unsigned*)(sm + SM_SBOFF);
    float*    spn    = sm + SM_PN;
    float*    spmin  = sm + SM_PMIN;
    float*    spmax  = sm + SM_PMAX;
    float*    soff   = sm + SM_OFF;
    float*    scent  = sm + SM_CENT;

    const int tid  = threadIdx.x;
    const int warp = tid >> 5;
    const int lane = tid & 31;

    for (int j = tid; j < 8192; j += K2_THREADS) { accOn[j] = 0.0f; accOff[j] = 0.0f; }
    for (int j = tid; j < 384; j += K2_THREADS) {
        spn[j] = plane_normal[j]; spmin[j] = plane_min[j]; spmax[j] = plane_max[j];
    }
    if (tid < 128) {
        soff[tid] = plane_center[tid * 3 + 0] * plane_normal[tid * 3 + 0]
                  + plane_center[tid * 3 + 1] * plane_normal[tid * 3 + 1]
                  + plane_center[tid * 3 + 2] * plane_normal[tid * 3 + 2];
    }
    if (tid < 3) scent[tid] = centers[tid];
    __syncthreads();

    float* outS  = out;
    float* outM  = out + PN;
    float* outOn = out + 2 * PN;
    float* outOf = out + 3 * PN;

    const float4* h2v = (const float4*)g_h2;
    float4* hsv = (float4*)hs;

    for (int c = blockIdx.x; c < NCHUNK; c += gridDim.x) {
        const int base = c * CHUNK;
        __syncthreads();   // previous chunk's phase B done before overwrite

        // stage h2 chunk
        for (int j = tid; j < CHUNK * 16; j += K2_THREADS)
            hsv[j] = h2v[(size_t)base * 16 + j];

        const int i = base + tid;
        const float clx = xyz[(size_t)i * 3 + 0] + scent[0];
        const float cly = xyz[(size_t)i * 3 + 1] + scent[1];
        const float clz = xyz[(size_t)i * 3 + 2] + scent[2];
        const float sc  = g_scores[i];
        const bool  pos = sc > 0.0f;

        // phase A: masks, big outputs, ballots
        for (int p = 0; p < 128; p++) {
            const float nx = spn[p * 3 + 0], ny = spn[p * 3 + 1], nz = spn[p * 3 + 2];
            float d = fabsf(clx * nx + cly * ny + clz * nz - soff[p]);
            bool m = d < 0.1f;
            {
                float mn = spmin[p * 3 + 0], mx = spmax[p * 3 + 0];
                m = m && ((mx == 0.0f) || (clx >= mn && clx < mx));
                mn = spmin[p * 3 + 1]; mx = spmax[p * 3 + 1];
                m = m && ((mx == 0.0f) || (cly >= mn && cly < mx));
                mn = spmin[p * 3 + 2]; mx = spmax[p * 3 + 2];
                m = m && ((mx == 0.0f) || (clz >= mn && clz < mx));
            }
            const size_t idx = (size_t)p * N_PTS + i;
            const bool on  = m && pos;
            const bool off = m && !pos;
            outS[idx]  = m   ? sc   : 0.0f;
            outM[idx]  = m   ? 1.0f : 0.0f;
            outOn[idx] = on  ? 1.0f : 0.0f;
            outOf[idx] = off ? 1.0f : 0.0f;
            const unsigned bo = __ballot_sync(0xFFFFFFFFu, on);
            const unsigned bf = __ballot_sync(0xFFFFFFFFu, off);
            if (lane == 0) { sbOn[warp * 128 + p] = bo; sbOff[warp * 128 + p] = bf; }
        }
        __syncthreads();

        // phase B: sparse masked max-pool from shared h2 cache
        const float2* hs2 = (const float2*)hs;
#pragma unroll
        for (int j = 0; j < 8; j++) {
            const int p = warp + j * 16;      // static plane ownership per warp
            float a0 = 0.0f, a1 = 0.0f, f0 = 0.0f, f1 = 0.0f;
            for (int g = 0; g < 16; g++) {
                unsigned bo = sbOn[g * 128 + p];
                while (bo) {
                    const int b = __ffs(bo) - 1; bo &= bo - 1;
                    const float2 v = hs2[(size_t)(g * 32 + b) * 32 + lane];
                    a0 = fmaxf(a0, v.x); a1 = fmaxf(a1, v.y);
                }
                unsigned bf = sbOff[g * 128 + p];
                while (bf) {
                    const int b = __ffs(bf) - 1; bf &= bf - 1;
                    const float2 v = hs2[(size_t)(g * 32 + b) * 32 + lane];
                    f0 = fmaxf(f0, v.x); f1 = fmaxf(f1, v.y);
                }
            }
            float* po = &accOn[p * 64 + lane * 2];
            po[0] = fmaxf(po[0], a0); po[1] = fmaxf(po[1], a1);
            po = &accOff[p * 64 + lane * 2];
            po[0] = fmaxf(po[0], f0); po[1] = fmaxf(po[1], f1);
        }
    }
    __syncthreads();

    // flush (values are >= 0, so int atomicMax == float max; region pre-zeroed)
    float* ofOn = out + 4 * PN;
    float* ofOf = ofOn + P_PL * D_F;
    for (int j = tid; j < P_PL * D_F; j += K2_THREADS) {
        atomicMax((int*)&ofOn[j], __float_as_int(accOn[j]));
        atomicMax((int*)&ofOf[j], __float_as_int(accOff[j]));
    }
}

// ---------------------------------------------------------------------------
// launch
// ---------------------------------------------------------------------------
extern "C" void kernel_launch(void* const* d_in, const int* in_sizes, int n_in,
                              void* d_out, int out_size)
{
    const float* feature      = (const float*)d_in[0];
    const float* feature_geo  = (const float*)d_in[1];
    const float* xyz          = (const float*)d_in[2];
    const float* centers      = (const float*)d_in[3];
    const float* plane_center = (const float*)d_in[4];
    const float* plane_normal = (const float*)d_in[5];
    const float* plane_min    = (const float*)d_in[6];
    const float* plane_max    = (const float*)d_in[7];
    const float* w1 = (const float*)d_in[8];
    const float* b1 = (const float*)d_in[9];
    const float* g1 = (const float*)d_in[10];
    const float* be1 = (const float*)d_in[11];
    const float* m1 = (const float*)d_in[12];
    const float* v1 = (const float*)d_in[13];
    const float* w2 = (const float*)d_in[14];
    const float* b2 = (const float*)d_in[15];
    const float* g2 = (const float*)d_in[16];
    const float* be2 = (const float*)d_in[17];
    const float* m2 = (const float*)d_in[18];
    const float* v2 = (const float*)d_in[19];
    const float* w3 = (const float*)d_in[20];
    const float* b3 = (const float*)d_in[21];

    float* out = (float*)d_out;

    // zero the pooled-feature output region
    k_init<<<(2 * P_PL * D_F + 255) / 256, 256>>>(out + 4 * PN);

    // per-point MLP (packed f32x2)
    k_mlp<<<N_PTS / MLP_T, MLP_T>>>(feature, feature_geo,
                                    w1, b1, g1, be1, m1, v1,
                                    w2, b2, g2, be2, m2, v2, w3, b3);

    // masks + outputs + pooling
    static bool attr_set = false;
    if (!attr_set) {
        cudaFuncSetAttribute(k_mask, cudaFuncAttributeMaxDynamicSharedMemorySize,
                             K2_SMEM_BYTES);
        attr_set = true;
    }
    k_mask<<<148, K2_THREADS, K2_SMEM_BYTES>>>(xyz, centers, plane_center,
                                               plane_normal, plane_min, plane_max,
                                               out);
}

// round 7
// speedup vs baseline: 1.1949x; 1.1949x over previous
#include <cuda_runtime.h>
#include <cstdint>

#define N_PTS 262144
#define P_PL  128
#define D_F   64
#define EPSV  1e-5f

#define PN ((size_t)P_PL * (size_t)N_PTS)   // 33,554,432

// Scratch (sanctioned: __device__ globals, no runtime allocation)
__device__ float g_h2[N_PTS * D_F];      // 67 MB
__device__ float g_scores[N_PTS];        // 1 MB

// ---------------------------------------------------------------------------
// packed f32x2 helpers (sm_100+ PTX; ptxas never emits FFMA2 from plain C++)
// ---------------------------------------------------------------------------
__device__ __forceinline__ void ffma2(unsigned long long& d,
                                      unsigned long long a,
                                      unsigned long long b) {
    asm("fma.rn.f32x2 %0, %1, %2, %0;" : "+l"(d) : "l"(a), "l"(b));
}
// d = d * s + t   (packed BN)
__device__ __forceinline__ void ffma2_bn(unsigned long long& d,
                                         unsigned long long s,
                                         unsigned long long t) {
    asm("fma.rn.f32x2 %0, %0, %1, %2;" : "+l"(d) : "l"(s), "l"(t));
}
__device__ __forceinline__ unsigned long long pk2(float lo, float hi) {
    unsigned long long r;
    asm("mov.b64 %0, {%1, %2};" : "=l"(r) : "f"(lo), "f"(hi));
    return r;
}
__device__ __forceinline__ void upk2(unsigned long long v, float& lo, float& hi) {
    asm("mov.b64 {%0, %1}, %2;" : "=f"(lo), "=f"(hi) : "l"(v));
}

// ---------------------------------------------------------------------------
// Kernel 1: per-point MLP with packed f32x2 FMAs (channel-pair packing).
// One thread per point, 128 threads/block. h1 kept PACKED in acc (no spills).
// Block 0 additionally zeroes the pooled-feature output region.
// ---------------------------------------------------------------------------
#define MLP_T 128

__global__ __launch_bounds__(MLP_T)
void k_mlp(const float* __restrict__ feature,
           const float* __restrict__ feature_geo,
           const float* __restrict__ w1, const float* __restrict__ b1,
           const float* __restrict__ g1, const float* __restrict__ be1,
           const float* __restrict__ m1, const float* __restrict__ v1,
           const float* __restrict__ w2, const float* __restrict__ b2,
           const float* __restrict__ g2, const float* __restrict__ be2,
           const float* __restrict__ m2, const float* __restrict__ v2,
           const float* __restrict__ w3, const float* __restrict__ b3,
           float* __restrict__ feat_out_zero)
{
    __shared__ __align__(16) float w1s[128 * 64];   // [k][d]
    __shared__ __align__(16) float w2s[64 * 64];    // [k][d]
    __shared__ __align__(16) float s1s[64], t1s[64], s2s[64], t2s[64], w3s[64];
    __shared__ float b3s;

    const int tid = threadIdx.x;

    // fold in the output zero-init (one block; overlapped with everything)
    if (blockIdx.x == 0) {
        float4* z = (float4*)feat_out_zero;
        for (int j = tid; j < 2 * P_PL * D_F / 4; j += MLP_T)
            z[j] = make_float4(0.f, 0.f, 0.f, 0.f);
    }

    for (int j = tid; j < 2048; j += MLP_T) ((float4*)w1s)[j] = ((const float4*)w1)[j];
    for (int j = tid; j < 1024; j += MLP_T) ((float4*)w2s)[j] = ((const float4*)w2)[j];
    if (tid < 64) {
        float s = g1[tid] * rsqrtf(v1[tid] + EPSV);
        s1s[tid] = s;
        t1s[tid] = (b1[tid] - m1[tid]) * s + be1[tid];
        s = g2[tid] * rsqrtf(v2[tid] + EPSV);
        s2s[tid] = s;
        t2s[tid] = (b2[tid] - m2[tid]) * s + be2[tid];
        w3s[tid] = w3[tid];
    }
    if (tid == 0) b3s = b3[0];
    __syncthreads();

    const int i = blockIdx.x * MLP_T + tid;

    // ---- layer 1: acc[dv] packs outputs (2dv, 2dv+1) ----
    unsigned long long acc[32];
#pragma unroll
    for (int d = 0; d < 32; d++) acc[d] = 0ull;

    const float4* fv = (const float4*)feature + (size_t)i * 16;
    const float4* gv = (const float4*)feature_geo + (size_t)i * 16;

#pragma unroll 1
    for (int q = 0; q < 16; q++) {
        float4 f = fv[q];
#pragma unroll
        for (int kk = 0; kk < 4; kk++) {
            float fk = (kk == 0) ? f.x : (kk == 1) ? f.y : (kk == 2) ? f.z : f.w;
            unsigned long long fp = pk2(fk, fk);
            const ulonglong2* wr = (const ulonglong2*)&w1s[(q * 4 + kk) * 64];
#pragma unroll
            for (int dv = 0; dv < 16; dv++) {
                ulonglong2 w = wr[dv];
                ffma2(acc[2 * dv + 0], fp, w.x);
                ffma2(acc[2 * dv + 1], fp, w.y);
            }
        }
    }
#pragma unroll 1
    for (int q = 0; q < 16; q++) {
        float4 f = gv[q];
#pragma unroll
        for (int kk = 0; kk < 4; kk++) {
            float fk = (kk == 0) ? f.x : (kk == 1) ? f.y : (kk == 2) ? f.z : f.w;
            unsigned long long fp = pk2(fk, fk);
            const ulonglong2* wr = (const ulonglong2*)&w1s[(64 + q * 4 + kk) * 64];
#pragma unroll
            for (int dv = 0; dv < 16; dv++) {
                ulonglong2 w = wr[dv];
                ffma2(acc[2 * dv + 0], fp, w.x);
                ffma2(acc[2 * dv + 1], fp, w.y);
            }
        }
    }

    // ---- BN + ReLU, IN PLACE, packed: acc now holds h1 pairs ----
#pragma unroll
    for (int dv = 0; dv < 32; dv++) {
        unsigned long long sp = *(const unsigned long long*)&s1s[2 * dv];
        unsigned long long tp = *(const unsigned long long*)&t1s[2 * dv];
        ffma2_bn(acc[dv], sp, tp);
        float x, y;
        upk2(acc[dv], x, y);
        acc[dv] = pk2(fmaxf(x, 0.0f), fmaxf(y, 0.0f));
    }

    // ---- layer 2 in two halves of 32 outputs (acc stays live, packed) ----
    unsigned long long score2 = 0ull;
#pragma unroll 1
    for (int half = 0; half < 2; half++) {
        unsigned long long a2[16];
#pragma unroll
        for (int d = 0; d < 16; d++) a2[d] = 0ull;
#pragma unroll 1
        for (int kp = 0; kp < 32; kp++) {       // k-pair = rows 2kp, 2kp+1
            float lo, hi;
            upk2(acc[kp], lo, hi);
            unsigned long long hpA = pk2(lo, lo);
            unsigned long long hpB = pk2(hi, hi);
            const ulonglong2* wrA = (const ulonglong2*)&w2s[(2 * kp + 0) * 64 + half * 32];
            const ulonglong2* wrB = (const ulonglong2*)&w2s[(2 * kp + 1) * 64 + half * 32];
#pragma unroll
            for (int dv = 0; dv < 8; dv++) {
                ulonglong2 wA = wrA[dv];
                ffma2(a2[2 * dv + 0], hpA, wA.x);
                ffma2(a2[2 * dv + 1], hpA, wA.y);
            }
#pragma unroll
            for (int dv = 0; dv < 8; dv++) {
                ulonglong2 wB = wrB[dv];
                ffma2(a2[2 * dv + 0], hpB, wB.x);
                ffma2(a2[2 * dv + 1], hpB, wB.y);
            }
        }
        // BN + ReLU + score accumulation + packed store
        ulonglong2* o2 = (ulonglong2*)&g_h2[(size_t)i * 64 + half * 32];
#pragma unroll
        for (int dv = 0; dv < 16; dv++) {
            const int d0 = half * 32 + dv * 2;
            unsigned long long sp = *(const unsigned long long*)&s2s[d0];
            unsigned long long tp = *(const unsigned long long*)&t2s[d0];
            ffma2_bn(a2[dv], sp, tp);
            float x, y;
            upk2(a2[dv], x, y);
            a2[dv] = pk2(fmaxf(x, 0.0f), fmaxf(y, 0.0f));
            unsigned long long wp = *(const unsigned long long*)&w3s[d0];
            ffma2(score2, a2[dv], wp);
        }
#pragma unroll
        for (int j = 0; j < 8; j++)
            o2[j] = make_ulonglong2(a2[2 * j], a2[2 * j + 1]);
    }
    float slo, shi;
    upk2(score2, slo, shi);
    g_scores[i] = fmaxf(slo + shi + b3s, 0.0f);
}

// ---------------------------------------------------------------------------
// Kernel 2: masks + 4 big outputs + masked max-pool via ballots
// Grid-stride over 512-point chunks; 512 threads/block; 1 block/SM (smem).
// ---------------------------------------------------------------------------
#define K2_THREADS 512
#define CHUNK 512
#define NCHUNK (N_PTS / CHUNK)   // 512

#define SM_HS      0
#define SM_ACCON   (SM_HS + CHUNK * 64)
#define SM_ACCOFF  (SM_ACCON + 8192)
#define SM_SBON    (SM_ACCOFF + 8192)           // as u32
#define SM_SBOFF   (SM_SBON + 2048)
#define SM_PN      (SM_SBOFF + 2048)
#define SM_PMIN    (SM_PN + 384)
#define SM_PMAX    (SM_PMIN + 384)
#define SM_OFF     (SM_PMAX + 384)
#define SM_CENT    (SM_OFF + 128)
#define SM_TOTALF  (SM_CENT + 4)
#define K2_SMEM_BYTES (SM_TOTALF * 4)

__global__ __launch_bounds__(K2_THREADS)
void k_mask(const float* __restrict__ xyz,
            const float* __restrict__ centers,
            const float* __restrict__ plane_center,
            const float* __restrict__ plane_normal,
            const float* __restrict__ plane_min,
            const float* __restrict__ plane_max,
            float* __restrict__ out)
{
    extern __shared__ float sm[];
    float*    hs     = sm + SM_HS;
    float*    accOn  = sm + SM_ACCON;
    float*    accOff = sm + SM_ACCOFF;
    unsigned* sbOn   = (unsigned*)(sm + SM_SBON);
    unsigned* sbOff  = (unsigned*)(sm + SM_SBOFF);
    float*    spn    = sm + SM_PN;
    float*    spmin  = sm + SM_PMIN;
    float*    spmax  = sm + SM_PMAX;
    float*    soff   = sm + SM_OFF;
    float*    scent  = sm + SM_CENT;

    const int tid  = threadIdx.x;
    const int warp = tid >> 5;
    const int lane = tid & 31;

    for (int j = tid; j < 8192; j += K2_THREADS) { accOn[j] = 0.0f; accOff[j] = 0.0f; }
    for (int j = tid; j < 384; j += K2_THREADS) {
        spn[j] = plane_normal[j]; spmin[j] = plane_min[j]; spmax[j] = plane_max[j];
    }
    if (tid < 128) {
        soff[tid] = plane_center[tid * 3 + 0] * plane_normal[tid * 3 + 0]
                  + plane_center[tid * 3 + 1] * plane_normal[tid * 3 + 1]
                  + plane_center[tid * 3 + 2] * plane_normal[tid * 3 + 2];
    }
    if (tid < 3) scent[tid] = centers[tid];
    __syncthreads();

    float* outS  = out;
    float* outM  = out + PN;
    float* outOn = out + 2 * PN;
    float* outOf = out + 3 * PN;

    const float4* h2v = (const float4*)g_h2;
    float4* hsv = (float4*)hs;

    for (int c = blockIdx.x; c < NCHUNK; c += gridDim.x) {
        const int base = c * CHUNK;
        __syncthreads();   // previous chunk's phase B done before overwrite

        // stage h2 chunk
        for (int j = tid; j < CHUNK * 16; j += K2_THREADS)
            hsv[j] = h2v[(size_t)base * 16 + j];

        const int i = base + tid;
        const float clx = xyz[(size_t)i * 3 + 0] + scent[0];
        const float cly = xyz[(size_t)i * 3 + 1] + scent[1];
        const float clz = xyz[(size_t)i * 3 + 2] + scent[2];
        const float sc  = g_scores[i];
        const bool  pos = sc > 0.0f;

        // phase A: masks, big outputs, ballots
        for (int p = 0; p < 128; p++) {
            const float nx = spn[p * 3 + 0], ny = spn[p * 3 + 1], nz = spn[p * 3 + 2];
            float d = fabsf(clx * nx + cly * ny + clz * nz - soff[p]);
            bool m = d < 0.1f;
            {
                float mn = spmin[p * 3 + 0], mx = spmax[p * 3 + 0];
                m = m && ((mx == 0.0f) || (clx >= mn && clx < mx));
                mn = spmin[p * 3 + 1]; mx = spmax[p * 3 + 1];
                m = m && ((mx == 0.0f) || (cly >= mn && cly < mx));
                mn = spmin[p * 3 + 2]; mx = spmax[p * 3 + 2];
                m = m && ((mx == 0.0f) || (clz >= mn && clz < mx));
            }
            const size_t idx = (size_t)p * N_PTS + i;
            const bool on  = m && pos;
            const bool off = m && !pos;
            outS[idx]  = m   ? sc   : 0.0f;
            outM[idx]  = m   ? 1.0f : 0.0f;
            outOn[idx] = on  ? 1.0f : 0.0f;
            outOf[idx] = off ? 1.0f : 0.0f;
            const unsigned bo = __ballot_sync(0xFFFFFFFFu, on);
            const unsigned bf = __ballot_sync(0xFFFFFFFFu, off);
            if (lane == 0) { sbOn[warp * 128 + p] = bo; sbOff[warp * 128 + p] = bf; }
        }
        __syncthreads();

        // phase B: sparse masked max-pool from shared h2 cache
        const float2* hs2 = (const float2*)hs;
#pragma unroll
        for (int j = 0; j < 8; j++) {
            const int p = warp + j * 16;      // static plane ownership per warp
            float a0 = 0.0f, a1 = 0.0f, f0 = 0.0f, f1 = 0.0f;
            for (int g = 0; g < 16; g++) {
                unsigned bo = sbOn[g * 128 + p];
                while (bo) {
                    const int b = __ffs(bo) - 1; bo &= bo - 1;
                    const float2 v = hs2[(size_t)(g * 32 + b) * 32 + lane];
                    a0 = fmaxf(a0, v.x); a1 = fmaxf(a1, v.y);
                }
                unsigned bf = sbOff[g * 128 + p];
                while (bf) {
                    const int b = __ffs(bf) - 1; bf &= bf - 1;
                    const float2 v = hs2[(size_t)(g * 32 + b) * 32 + lane];
                    f0 = fmaxf(f0, v.x); f1 = fmaxf(f1, v.y);
                }
            }
            float* po = &accOn[p * 64 + lane * 2];
            po[0] = fmaxf(po[0], a0); po[1] = fmaxf(po[1], a1);
            po = &accOff[p * 64 + lane * 2];
            po[0] = fmaxf(po[0], f0); po[1] = fmaxf(po[1], f1);
        }
    }
    __syncthreads();

    // flush (values are >= 0, so int atomicMax == float max; region pre-zeroed)
    float* ofOn = out + 4 * PN;
    float* ofOf = ofOn + P_PL * D_F;
    for (int j = tid; j < P_PL * D_F; j += K2_THREADS) {
        atomicMax((int*)&ofOn[j], __float_as_int(accOn[j]));
        atomicMax((int*)&ofOf[j], __float_as_int(accOff[j]));
    }
}

// ---------------------------------------------------------------------------
// launch
// ---------------------------------------------------------------------------
extern "C" void kernel_launch(void* const* d_in, const int* in_sizes, int n_in,
                              void* d_out, int out_size)
{
    const float* feature      = (const float*)d_in[0];
    const float* feature_geo  = (const float*)d_in[1];
    const float* xyz          = (const float*)d_in[2];
    const float* centers      = (const float*)d_in[3];
    const float* plane_center = (const float*)d_in[4];
    const float* plane_normal = (const float*)d_in[5];
    const float* plane_min    = (const float*)d_in[6];
    const float* plane_max    = (const float*)d_in[7];
    const float* w1 = (const float*)d_in[8];
    const float* b1 = (const float*)d_in[9];
    const float* g1 = (const float*)d_in[10];
    const float* be1 = (const float*)d_in[11];
    const float* m1 = (const float*)d_in[12];
    const float* v1 = (const float*)d_in[13];
    const float* w2 = (const float*)d_in[14];
    const float* b2 = (const float*)d_in[15];
    const float* g2 = (const float*)d_in[16];
    const float* be2 = (const float*)d_in[17];
    const float* m2 = (const float*)d_in[18];
    const float* v2 = (const float*)d_in[19];
    const float* w3 = (const float*)d_in[20];
    const float* b3 = (const float*)d_in[21];

    float* out = (float*)d_out;

    // per-point MLP (packed f32x2, no spills) + folded output zero-init
    k_mlp<<<N_PTS / MLP_T, MLP_T>>>(feature, feature_geo,
                                    w1, b1, g1, be1, m1, v1,
                                    w2, b2, g2, be2, m2, v2, w3, b3,
                                    out + 4 * PN);

    // masks + outputs + pooling
    static bool attr_set = false;
    if (!attr_set) {
        cudaFuncSetAttribute(k_mask, cudaFuncAttributeMaxDynamicSharedMemorySize,
                             K2_SMEM_BYTES);
        attr_set = true;
    }
    k_mask<<<148, K2_THREADS, K2_SMEM_BYTES>>>(xyz, centers, plane_center,
                                               plane_normal, plane_min, plane_max,
                                               out);
}